// round 5
// baseline (speedup 1.0000x reference)
#include <cuda_runtime.h>
#include <cuda_bf16.h>
#include <cstdint>

// LinearAttention B=4, N=4096, D=1024 fp32
// bf16x3 split (hi/lo, 3 passes) on warp-level mma.sync (base compute_103 ISA).
// Round 5: 128x256 CTA tile, 64x64 warp tile (3:1 MMA:ldsm), 3-stage pipeline.

#define Bv 4
#define Nv 4096
#define Dv 1024
#define BNROWS (Bv*Nv)            // 16384

#define BM 128
#define BN 256
#define BKB 32                    // bf16 K per stage (64B rows)
#define GT 256                    // 8 warps

#define ASZ   8192                // A operand tile (128*32*2B)
#define BSZ   16384               // B operand tile (256*32*2B)
#define STAGE (2*ASZ + 2*BSZ)     // 49152
#define NSTG  3
#define SMEM_TOTAL (NSTG*STAGE)   // 147456

// ------------------------------ scratch -----------------------------------
__device__ __align__(16) __nv_bfloat16 g_XH [(size_t)BNROWS*Dv];
__device__ __align__(16) __nv_bfloat16 g_XL [(size_t)BNROWS*Dv];
__device__ __align__(16) __nv_bfloat16 g_WTH[4][1024*1024];
__device__ __align__(16) __nv_bfloat16 g_WTL[4][1024*1024];
__device__ __align__(16) float         g_Pf [4][(size_t)BNROWS*Dv];   // ql,qr,k,v fp32
__device__ __align__(16) __nv_bfloat16 g_QH [(size_t)BNROWS*Dv];
__device__ __align__(16) __nv_bfloat16 g_QLo[(size_t)BNROWS*Dv];
__device__ __align__(16) __nv_bfloat16 g_KTH[(size_t)Bv*Dv*Nv];
__device__ __align__(16) __nv_bfloat16 g_KTL[(size_t)Bv*Dv*Nv];
__device__ __align__(16) __nv_bfloat16 g_VTH[(size_t)Bv*Dv*Nv];
__device__ __align__(16) __nv_bfloat16 g_VTL[(size_t)Bv*Dv*Nv];
__device__ __align__(16) float         g_KVf[(size_t)Bv*Dv*Dv];
__device__ __align__(16) __nv_bfloat16 g_KVTH[(size_t)Bv*Dv*Dv];
__device__ __align__(16) __nv_bfloat16 g_KVTL[(size_t)Bv*Dv*Dv];

// ------------------------------ helpers ------------------------------------
#define SWZ64(x) ((x) ^ (((x) >> 3) & 0x30))

__device__ __forceinline__ uint32_t s2u(const void* p) {
    uint32_t a;
    asm("{ .reg .u64 t; cvta.to.shared.u64 t, %1; cvt.u32.u64 %0, t; }" : "=r"(a) : "l"(p));
    return a;
}
__device__ __forceinline__ void cpa16(uint32_t dst, const void* src) {
    asm volatile("cp.async.cg.shared.global [%0], [%1], 16;" :: "r"(dst), "l"(src));
}
#define CPC() asm volatile("cp.async.commit_group;" ::: "memory")

__device__ __forceinline__ void ldsm4(uint32_t* r, uint32_t addr) {
    asm volatile("ldmatrix.sync.aligned.m8n8.x4.shared.b16 {%0,%1,%2,%3}, [%4];"
                 : "=r"(r[0]), "=r"(r[1]), "=r"(r[2]), "=r"(r[3]) : "r"(addr));
}
__device__ __forceinline__ void mma16816(float* c, const uint32_t* a, const uint32_t* b) {
    asm volatile(
        "mma.sync.aligned.m16n8k16.row.col.f32.bf16.bf16.f32 "
        "{%0,%1,%2,%3}, {%4,%5,%6,%7}, {%8,%9}, {%0,%1,%2,%3};"
        : "+f"(c[0]), "+f"(c[1]), "+f"(c[2]), "+f"(c[3])
        : "r"(a[0]), "r"(a[1]), "r"(a[2]), "r"(a[3]), "r"(b[0]), "r"(b[1]));
}

// ------------------------------ GEMM kernel --------------------------------
// C[M,N] fp32 = (Ah+Al)[M,K] * ((Bh+Bl)[N,K])^T, all K-major, batched on z.
__global__ __launch_bounds__(GT, 1)
void gemm_bf16x3(const __nv_bfloat16* __restrict__ Ahg, const __nv_bfloat16* __restrict__ Alg,
                 const __nv_bfloat16* __restrict__ Bhg, const __nv_bfloat16* __restrict__ Blg,
                 float* __restrict__ Cg, int M, int N, int Kg,
                 long sA, long sB, long sC)
{
    extern __shared__ char sm[];
    const uint32_t smu = s2u(sm);
    const int tid = threadIdx.x, lane = tid & 31, wid = tid >> 5;
    const int bm = blockIdx.y * BM, bn = blockIdx.x * BN;
    const int wm = (wid & 1) * 64, wn = (wid >> 1) * 64;

    const __nv_bfloat16* Ah = Ahg + (size_t)blockIdx.z * sA;
    const __nv_bfloat16* Al = Alg + (size_t)blockIdx.z * sA;
    const __nv_bfloat16* Bh = Bhg + (size_t)blockIdx.z * sB;
    const __nv_bfloat16* Bl = Blg + (size_t)blockIdx.z * sB;
    float* Cb = Cg + (size_t)blockIdx.z * sC;

    // gmem load indexing: A tile 512 16B-chunks (2/thread), B tile 1024 (4/thread)
    const int rr = tid >> 2, cg = tid & 3;           // base row, 16B col group
    uint32_t soA[2], soB[4];
#pragma unroll
    for (int j = 0; j < 2; j++) soA[j] = SWZ64((uint32_t)((rr + j*64) * 64 + cg * 16));
#pragma unroll
    for (int j = 0; j < 4; j++) soB[j] = SWZ64((uint32_t)((rr + j*64) * 64 + cg * 16));
    const __nv_bfloat16* gAh = Ah + (size_t)(bm + rr) * Kg + cg * 8;
    const __nv_bfloat16* gAl = Al + (size_t)(bm + rr) * Kg + cg * 8;
    const __nv_bfloat16* gBh = Bh + (size_t)(bn + rr) * Kg + cg * 8;
    const __nv_bfloat16* gBl = Bl + (size_t)(bn + rr) * Kg + cg * 8;
    const size_t rstep = (size_t)64 * Kg;

    // ldmatrix fragment offsets (relative to operand tile base)
    uint32_t aoff[2][4], boff[2][4];
    {
        uint32_t arow = (uint32_t)(wm + (lane & 15));
        uint32_t acol = (uint32_t)((lane >> 4) * 16);
        uint32_t brow = (uint32_t)(wn + ((lane >> 4) << 3) + (lane & 7));
        uint32_t bcol = (uint32_t)(((lane >> 3) & 1) * 16);
#pragma unroll
        for (int ks = 0; ks < 2; ks++) {
#pragma unroll
            for (int mi = 0; mi < 4; mi++)
                aoff[ks][mi] = SWZ64((arow + mi * 16) * 64 + ks * 32 + acol);
#pragma unroll
            for (int g = 0; g < 4; g++)
                boff[ks][g] = SWZ64((brow + g * 16) * 64 + ks * 32 + bcol);
        }
    }

    float acc[4][8][4];
#pragma unroll
    for (int mi = 0; mi < 4; mi++)
#pragma unroll
        for (int ni = 0; ni < 8; ni++)
#pragma unroll
            for (int j = 0; j < 4; j++) acc[mi][ni][j] = 0.0f;

    const int nch = Kg / BKB;

    auto load_stage = [&](int c) {
        const uint32_t st = smu + (uint32_t)(c % NSTG) * STAGE;
        const int k0 = c * BKB;
#pragma unroll
        for (int j = 0; j < 2; j++) {
            cpa16(st + soA[j],        gAh + k0 + j * rstep);
            cpa16(st + ASZ + soA[j],  gAl + k0 + j * rstep);
        }
#pragma unroll
        for (int j = 0; j < 4; j++) {
            cpa16(st + 2*ASZ + soB[j],        gBh + k0 + j * rstep);
            cpa16(st + 2*ASZ + BSZ + soB[j],  gBl + k0 + j * rstep);
        }
        CPC();
    };

    load_stage(0);
    load_stage(1);

    for (int c = 0; c < nch; ++c) {
        asm volatile("cp.async.wait_group 1;" ::: "memory");
        __syncthreads();
        if (c + 2 < nch) load_stage(c + 2);

        const uint32_t st = smu + (uint32_t)(c % NSTG) * STAGE;
#pragma unroll
        for (int ks = 0; ks < 2; ks++) {
            uint32_t ah[4][4], al[4][4];
#pragma unroll
            for (int mi = 0; mi < 4; mi++) {
                ldsm4(ah[mi], st + aoff[ks][mi]);
                ldsm4(al[mi], st + ASZ + aoff[ks][mi]);
            }
#pragma unroll
            for (int g = 0; g < 4; g++) {
                uint32_t tbh[4], tbl[4];
                ldsm4(tbh, st + 2*ASZ + boff[ks][g]);
                ldsm4(tbl, st + 2*ASZ + BSZ + boff[ks][g]);
#pragma unroll
                for (int mi = 0; mi < 4; mi++) {
                    mma16816(acc[mi][2*g],   ah[mi], tbh);
                    mma16816(acc[mi][2*g],   ah[mi], tbl);
                    mma16816(acc[mi][2*g],   al[mi], tbh);
                    mma16816(acc[mi][2*g+1], ah[mi], tbh + 2);
                    mma16816(acc[mi][2*g+1], ah[mi], tbl + 2);
                    mma16816(acc[mi][2*g+1], al[mi], tbh + 2);
                }
            }
        }
    }

    // epilogue: m16n8 fragment -> C
#pragma unroll
    for (int mi = 0; mi < 4; mi++) {
        int rA = bm + wm + mi * 16 + (lane >> 2);
#pragma unroll
        for (int ni = 0; ni < 8; ni++) {
            int col = bn + wn + ni * 8 + (lane & 3) * 2;
            *(float2*)(Cb + (size_t)rA * N + col)       = make_float2(acc[mi][ni][0], acc[mi][ni][1]);
            *(float2*)(Cb + (size_t)(rA + 8) * N + col) = make_float2(acc[mi][ni][2], acc[mi][ni][3]);
        }
    }
}

// --------------------------- conversion kernels ----------------------------
__device__ __forceinline__ void split1(float f, __nv_bfloat16& h, __nv_bfloat16& l) {
    h = __float2bfloat16(f);
    l = __float2bfloat16(f - __bfloat162float(h));
}

__global__ void split_plain(const float* __restrict__ in,
                            __nv_bfloat16* __restrict__ oh, __nv_bfloat16* __restrict__ ol) {
    size_t i = (size_t)blockIdx.x * blockDim.x + threadIdx.x;
    float4 f = ((const float4*)in)[i];
    __nv_bfloat16 h0,h1,h2,h3,l0,l1,l2,l3;
    split1(f.x,h0,l0); split1(f.y,h1,l1); split1(f.z,h2,l2); split1(f.w,h3,l3);
    ((__nv_bfloat162*)oh)[i*2]   = __halves2bfloat162(h0,h1);
    ((__nv_bfloat162*)oh)[i*2+1] = __halves2bfloat162(h2,h3);
    ((__nv_bfloat162*)ol)[i*2]   = __halves2bfloat162(l0,l1);
    ((__nv_bfloat162*)ol)[i*2+1] = __halves2bfloat162(l2,l3);
}

__global__ void gate_split(const float* __restrict__ a, const float* __restrict__ b,
                           __nv_bfloat16* __restrict__ oh, __nv_bfloat16* __restrict__ ol) {
    size_t i = (size_t)blockIdx.x * blockDim.x + threadIdx.x;
    float4 fa = ((const float4*)a)[i];
    float4 fb = ((const float4*)b)[i];
    fa.x *= fb.x; fa.y *= fb.y; fa.z *= fb.z; fa.w *= fb.w;
    __nv_bfloat16 h0,h1,h2,h3,l0,l1,l2,l3;
    split1(fa.x,h0,l0); split1(fa.y,h1,l1); split1(fa.z,h2,l2); split1(fa.w,h3,l3);
    ((__nv_bfloat162*)oh)[i*2]   = __halves2bfloat162(h0,h1);
    ((__nv_bfloat162*)oh)[i*2+1] = __halves2bfloat162(h2,h3);
    ((__nv_bfloat162*)ol)[i*2]   = __halves2bfloat162(l0,l1);
    ((__nv_bfloat162*)ol)[i*2+1] = __halves2bfloat162(l2,l3);
}

// in [R,C] fp32 (batch z) -> out [C,R] bf16 hi/lo
__global__ void split_transpose(const float* __restrict__ in,
                                __nv_bfloat16* __restrict__ oh, __nv_bfloat16* __restrict__ ol,
                                int R, int Cc, long sIn, long sOut) {
    __shared__ float t[32][33];
    const float* ib = in + (size_t)blockIdx.z * sIn;
    __nv_bfloat16* ohb = oh + (size_t)blockIdx.z * sOut;
    __nv_bfloat16* olb = ol + (size_t)blockIdx.z * sOut;
    int c0 = blockIdx.x * 32, r0 = blockIdx.y * 32;
    int tx = threadIdx.x, ty = threadIdx.y;
#pragma unroll
    for (int i = 0; i < 4; i++)
        t[ty + i*8][tx] = ib[(size_t)(r0 + ty + i*8) * Cc + c0 + tx];
    __syncthreads();
#pragma unroll
    for (int i = 0; i < 4; i++) {
        int oc = c0 + ty + i*8, orow = r0 + tx;
        float f = t[tx][ty + i*8];
        __nv_bfloat16 h, l; split1(f, h, l);
        ohb[(size_t)oc * R + orow] = h;
        olb[(size_t)oc * R + orow] = l;
    }
}

// ------------------------------- launch ------------------------------------
extern "C" void kernel_launch(void* const* d_in, const int* in_sizes, int n_in,
                              void* d_out, int out_size) {
    const float* x   = (const float*)d_in[0];
    const float* w[4] = { (const float*)d_in[1], (const float*)d_in[2],
                          (const float*)d_in[3], (const float*)d_in[4] };
    float* out = (float*)d_out;

    __nv_bfloat16 *XH,*XL,*WTH,*WTL,*QH,*QLo,*KTH,*KTL,*VTH,*VTL,*KVTH,*KVTL;
    float *Pf,*KVf;
    cudaGetSymbolAddress((void**)&XH,  g_XH);   cudaGetSymbolAddress((void**)&XL,  g_XL);
    cudaGetSymbolAddress((void**)&WTH, g_WTH);  cudaGetSymbolAddress((void**)&WTL, g_WTL);
    cudaGetSymbolAddress((void**)&Pf,  g_Pf);
    cudaGetSymbolAddress((void**)&QH,  g_QH);   cudaGetSymbolAddress((void**)&QLo, g_QLo);
    cudaGetSymbolAddress((void**)&KTH, g_KTH);  cudaGetSymbolAddress((void**)&KTL, g_KTL);
    cudaGetSymbolAddress((void**)&VTH, g_VTH);  cudaGetSymbolAddress((void**)&VTL, g_VTL);
    cudaGetSymbolAddress((void**)&KVf, g_KVf);
    cudaGetSymbolAddress((void**)&KVTH,g_KVTH); cudaGetSymbolAddress((void**)&KVTL,g_KVTL);

    cudaFuncSetAttribute(gemm_bf16x3, cudaFuncAttributeMaxDynamicSharedMemorySize, SMEM_TOTAL);

    const size_t DDe = (size_t)Dv * Dv;
    const size_t PNe = (size_t)BNROWS * Dv;
    dim3 tb32(32, 8);

    // 1) splits of x and W^T
    split_plain<<<(unsigned)(PNe/4/256), 256>>>(x, XH, XL);
    for (int i = 0; i < 4; i++)
        split_transpose<<<dim3(Dv/32, Dv/32, 1), tb32>>>(w[i], WTH + i*DDe, WTL + i*DDe,
                                                         Dv, Dv, 0, 0);
    // 2) all 4 projections in ONE launch: z indexes weight (sB=DDe) and output (sC=PNe)
    gemm_bf16x3<<<dim3(Dv/BN, BNROWS/BM, 4), GT, SMEM_TOTAL>>>(
        XH, XL, (const __nv_bfloat16*)WTH, (const __nv_bfloat16*)WTL,
        Pf, BNROWS, Dv, Dv, 0, (long)DDe, (long)PNe);

    float* QLf = Pf;          float* QRf = Pf + PNe;
    float* Kf  = Pf + 2*PNe;  float* Vf  = Pf + 3*PNe;

    // 3) gate + split q
    gate_split<<<(unsigned)(PNe/4/256), 256>>>(QLf, QRf, QH, QLo);

    // 4) transpose-splits of k, v  ([Nv,Dv] -> [Dv,Nv] per batch)
    split_transpose<<<dim3(Dv/32, Nv/32, Bv), tb32>>>(Kf, KTH, KTL, Nv, Dv,
                                                      (long)Nv*Dv, (long)Nv*Dv);
    split_transpose<<<dim3(Dv/32, Nv/32, Bv), tb32>>>(Vf, VTH, VTL, Nv, Dv,
                                                      (long)Nv*Dv, (long)Nv*Dv);
    // 5) kv[b] = k^T @ v : A=kT[Dv,Nv], B=vT[Dv,Nv] (both K(=Nv)-major)
    gemm_bf16x3<<<dim3(Dv/BN, Dv/BM, Bv), GT, SMEM_TOTAL>>>(
        KTH, KTL, VTH, VTL, KVf, Dv, Dv, Nv,
        (long)Dv*Nv, (long)Dv*Nv, (long)DDe);

    // 6) transpose-split kv ([Dv,Dv] -> [Dv,Dv]^T per batch)
    split_transpose<<<dim3(Dv/32, Dv/32, Bv), tb32>>>(KVf, KVTH, KVTL, Dv, Dv,
                                                      (long)DDe, (long)DDe);
    // 7) out[b] = q @ kv : A=q[Nv,Dv], B=kv^T[Dv,Dv] (K(=Dv)-major)
    gemm_bf16x3<<<dim3(Dv/BN, Nv/BM, Bv), GT, SMEM_TOTAL>>>(
        QH, QLo, KVTH, KVTL, out, Nv, Dv, Dv,
        (long)Nv*Dv, (long)DDe, (long)Nv*Dv);
}

// round 6
// speedup vs baseline: 1.0348x; 1.0348x over previous
#include <cuda_runtime.h>
#include <cuda_bf16.h>
#include <cstdint>

// LinearAttention B=4, N=4096, D=1024 fp32 — bf16x3 mma.sync, fused epilogues.
//  R6: dual-B projection kernels (gate fused; k/v split-transposed in epilogue),
//      kv GEMM writes kv^T split directly. No fp32 intermediates.

#define Bv 4
#define Nv 4096
#define Dv 1024
#define BNROWS (Bv*Nv)            // 16384

#define GT 256                    // 8 warps
#define ASZ 8192                  // 128 rows x 32 bf16 (64B) operand tile

#define STAGE1 (4*ASZ)            // single-GEMM stage: Ah,Al,Bh,Bl
#define NST1 4
#define SMEM1 (NST1*STAGE1)       // 131072

#define STAGE2 (6*ASZ)            // dual-GEMM stage: Ah,Al,B1h,B1l,B2h,B2l
#define NST2 3
#define SMEM2 (NST2*STAGE2)       // 147456

#define SWZ64(x) ((x) ^ (((x) >> 3) & 0x30))

// ------------------------------ scratch -----------------------------------
__device__ __align__(16) __nv_bfloat16 g_XH [(size_t)BNROWS*Dv];
__device__ __align__(16) __nv_bfloat16 g_XL [(size_t)BNROWS*Dv];
__device__ __align__(16) __nv_bfloat16 g_WTH[4][1024*1024];
__device__ __align__(16) __nv_bfloat16 g_WTL[4][1024*1024];
__device__ __align__(16) __nv_bfloat16 g_QH [(size_t)BNROWS*Dv];
__device__ __align__(16) __nv_bfloat16 g_QLo[(size_t)BNROWS*Dv];
__device__ __align__(16) __nv_bfloat16 g_KTH[(size_t)Bv*Dv*Nv];
__device__ __align__(16) __nv_bfloat16 g_KTL[(size_t)Bv*Dv*Nv];
__device__ __align__(16) __nv_bfloat16 g_VTH[(size_t)Bv*Dv*Nv];
__device__ __align__(16) __nv_bfloat16 g_VTL[(size_t)Bv*Dv*Nv];
__device__ __align__(16) __nv_bfloat16 g_KVTH[(size_t)Bv*Dv*Dv];
__device__ __align__(16) __nv_bfloat16 g_KVTL[(size_t)Bv*Dv*Dv];

// ------------------------------ helpers ------------------------------------
__device__ __forceinline__ uint32_t s2u(const void* p) {
    uint32_t a;
    asm("{ .reg .u64 t; cvta.to.shared.u64 t, %1; cvt.u32.u64 %0, t; }" : "=r"(a) : "l"(p));
    return a;
}
__device__ __forceinline__ void cpa16(uint32_t dst, const void* src) {
    asm volatile("cp.async.cg.shared.global [%0], [%1], 16;" :: "r"(dst), "l"(src));
}
#define CPC() asm volatile("cp.async.commit_group;" ::: "memory")

__device__ __forceinline__ void ldsm4(uint32_t* r, uint32_t addr) {
    asm volatile("ldmatrix.sync.aligned.m8n8.x4.shared.b16 {%0,%1,%2,%3}, [%4];"
                 : "=r"(r[0]), "=r"(r[1]), "=r"(r[2]), "=r"(r[3]) : "r"(addr));
}
__device__ __forceinline__ void mma16816(float* c, const uint32_t* a, const uint32_t* b) {
    asm volatile(
        "mma.sync.aligned.m16n8k16.row.col.f32.bf16.bf16.f32 "
        "{%0,%1,%2,%3}, {%4,%5,%6,%7}, {%8,%9}, {%0,%1,%2,%3};"
        : "+f"(c[0]), "+f"(c[1]), "+f"(c[2]), "+f"(c[3])
        : "r"(a[0]), "r"(a[1]), "r"(a[2]), "r"(a[3]), "r"(b[0]), "r"(b[1]));
}

__device__ __forceinline__ uint32_t pack_hl(float f) {
    __nv_bfloat16 h = __float2bfloat16(f);
    __nv_bfloat16 l = __float2bfloat16(f - __bfloat162float(h));
    return ((uint32_t)__bfloat16_as_ushort(h) << 16) | __bfloat16_as_ushort(l);
}
__device__ __forceinline__ void split2pack(float f0, float f1, uint32_t& wh, uint32_t& wl) {
    __nv_bfloat16 h0 = __float2bfloat16(f0);
    __nv_bfloat16 h1 = __float2bfloat16(f1);
    __nv_bfloat16 l0 = __float2bfloat16(f0 - __bfloat162float(h0));
    __nv_bfloat16 l1 = __float2bfloat16(f1 - __bfloat162float(h1));
    wh = ((uint32_t)__bfloat16_as_ushort(h1) << 16) | __bfloat16_as_ushort(h0);
    wl = ((uint32_t)__bfloat16_as_ushort(l1) << 16) | __bfloat16_as_ushort(l0);
}

// Split-transpose epilogue: 128x128 C tile (fragments) -> OH/OL rows (bn+d), cols bm..
// SMEM scratch: 128*133 uint32 packed (hi<<16 | lo). ldo = output row length.
__device__ __forceinline__ void epi_splitT(
    const float (&acc)[4][4][4], char* sm,
    int wm, int wn, int lane, int tid,
    __nv_bfloat16* __restrict__ OH, __nv_bfloat16* __restrict__ OL,
    size_t base, int ldo)
{
    __syncthreads();                       // SMEM handoff (mainloop / prev epi)
    uint32_t* s32 = (uint32_t*)sm;
#pragma unroll
    for (int mi = 0; mi < 4; mi++) {
        int r = wm + mi * 16 + (lane >> 2);
#pragma unroll
        for (int ni = 0; ni < 4; ni++) {
            int c = wn + ni * 8 + (lane & 3) * 2;
            s32[r * 133 + c]           = pack_hl(acc[mi][ni][0]);
            s32[r * 133 + c + 1]       = pack_hl(acc[mi][ni][1]);
            s32[(r + 8) * 133 + c]     = pack_hl(acc[mi][ni][2]);
            s32[(r + 8) * 133 + c + 1] = pack_hl(acc[mi][ni][3]);
        }
    }
    __syncthreads();
    int d = tid >> 1, nb = (tid & 1) * 64;
    __nv_bfloat16* rh = OH + base + (size_t)d * ldo + nb;
    __nv_bfloat16* rl = OL + base + (size_t)d * ldo + nb;
#pragma unroll
    for (int j = 0; j < 8; j++) {
        alignas(16) __nv_bfloat16 hb[8], lb[8];
#pragma unroll
        for (int i = 0; i < 8; i++) {
            uint32_t w = s32[(nb + j * 8 + i) * 133 + d];
            hb[i] = __ushort_as_bfloat16((unsigned short)(w >> 16));
            lb[i] = __ushort_as_bfloat16((unsigned short)(w & 0xFFFFu));
        }
        *(uint4*)(rh + j * 8) = *(const uint4*)hb;
        *(uint4*)(rl + j * 8) = *(const uint4*)lb;
    }
}

// --------------------- single-B GEMM (3-pass bf16x3) ------------------------
// C = (Ah+Al)[M,K] @ ((Bh+Bl)[N,K])^T. MODE 0: fp32 straight; MODE 1: splitT.
template<int MODE>
__global__ __launch_bounds__(GT, 1)
void gemm3(const __nv_bfloat16* __restrict__ Ahg, const __nv_bfloat16* __restrict__ Alg,
           const __nv_bfloat16* __restrict__ Bhg, const __nv_bfloat16* __restrict__ Blg,
           float* __restrict__ Cf,
           __nv_bfloat16* __restrict__ OH, __nv_bfloat16* __restrict__ OL,
           int M, int N, int Kg, long sA, long sB, long sO)
{
    extern __shared__ char sm[];
    const uint32_t smu = s2u(sm);
    const int tid = threadIdx.x, lane = tid & 31, wid = tid >> 5;
    const int bm = blockIdx.y * 128, bn = blockIdx.x * 128;
    const int wm = (wid & 1) * 64, wn = (wid >> 1) * 32;

    const __nv_bfloat16* Ah = Ahg + (size_t)blockIdx.z * sA;
    const __nv_bfloat16* Al = Alg + (size_t)blockIdx.z * sA;
    const __nv_bfloat16* Bh = Bhg + (size_t)blockIdx.z * sB;
    const __nv_bfloat16* Bl = Blg + (size_t)blockIdx.z * sB;

    const int rr = tid >> 2, cg = tid & 3;
    const uint32_t so0 = SWZ64((uint32_t)(rr * 64 + cg * 16));
    const uint32_t so1 = SWZ64((uint32_t)((rr + 64) * 64 + cg * 16));
    const __nv_bfloat16* gAh = Ah + (size_t)(bm + rr) * Kg + cg * 8;
    const __nv_bfloat16* gAl = Al + (size_t)(bm + rr) * Kg + cg * 8;
    const __nv_bfloat16* gBh = Bh + (size_t)(bn + rr) * Kg + cg * 8;
    const __nv_bfloat16* gBl = Bl + (size_t)(bn + rr) * Kg + cg * 8;
    const size_t rstep = (size_t)64 * Kg;

    uint32_t aoff[2][4], boff[2][2];
    {
        uint32_t arow = (uint32_t)(wm + (lane & 15));
        uint32_t acol = (uint32_t)((lane >> 4) * 16);
        uint32_t brow = (uint32_t)(wn + ((lane >> 4) << 3) + (lane & 7));
        uint32_t bcol = (uint32_t)(((lane >> 3) & 1) * 16);
#pragma unroll
        for (int ks = 0; ks < 2; ks++) {
#pragma unroll
            for (int mi = 0; mi < 4; mi++)
                aoff[ks][mi] = SWZ64((arow + mi * 16) * 64 + ks * 32 + acol);
#pragma unroll
            for (int g = 0; g < 2; g++)
                boff[ks][g] = SWZ64((brow + g * 16) * 64 + ks * 32 + bcol);
        }
    }

    float acc[4][4][4];
#pragma unroll
    for (int mi = 0; mi < 4; mi++)
#pragma unroll
        for (int ni = 0; ni < 4; ni++)
#pragma unroll
            for (int j = 0; j < 4; j++) acc[mi][ni][j] = 0.0f;

    const int nch = Kg / 32;
    auto load_stage = [&](int c) {
        const uint32_t st = smu + (uint32_t)(c & (NST1 - 1)) * STAGE1;
        const int k0 = c * 32;
        cpa16(st + so0,          gAh + k0);
        cpa16(st + so1,          gAh + k0 + rstep);
        cpa16(st + ASZ + so0,    gAl + k0);
        cpa16(st + ASZ + so1,    gAl + k0 + rstep);
        cpa16(st + 2*ASZ + so0,  gBh + k0);
        cpa16(st + 2*ASZ + so1,  gBh + k0 + rstep);
        cpa16(st + 3*ASZ + so0,  gBl + k0);
        cpa16(st + 3*ASZ + so1,  gBl + k0 + rstep);
        CPC();
    };

    load_stage(0); load_stage(1); load_stage(2);

    for (int c = 0; c < nch; ++c) {
        asm volatile("cp.async.wait_group 2;" ::: "memory");
        __syncthreads();
        if (c + 3 < nch) load_stage(c + 3);

        const uint32_t st = smu + (uint32_t)(c & (NST1 - 1)) * STAGE1;
#pragma unroll
        for (int ks = 0; ks < 2; ks++) {
            uint32_t ah[4][4], al[4][4];
#pragma unroll
            for (int mi = 0; mi < 4; mi++) {
                ldsm4(ah[mi], st + aoff[ks][mi]);
                ldsm4(al[mi], st + ASZ + aoff[ks][mi]);
            }
#pragma unroll
            for (int g = 0; g < 2; g++) {
                uint32_t tbh[4], tbl[4];
                ldsm4(tbh, st + 2*ASZ + boff[ks][g]);
                ldsm4(tbl, st + 3*ASZ + boff[ks][g]);
#pragma unroll
                for (int mi = 0; mi < 4; mi++) {
                    mma16816(acc[mi][2*g],   ah[mi], tbh);
                    mma16816(acc[mi][2*g],   ah[mi], tbl);
                    mma16816(acc[mi][2*g],   al[mi], tbh);
                    mma16816(acc[mi][2*g+1], ah[mi], tbh + 2);
                    mma16816(acc[mi][2*g+1], ah[mi], tbl + 2);
                    mma16816(acc[mi][2*g+1], al[mi], tbh + 2);
                }
            }
        }
    }

    if (MODE == 0) {
        float* Cb = Cf + (size_t)blockIdx.z * sO;
#pragma unroll
        for (int mi = 0; mi < 4; mi++) {
            int rA = bm + wm + mi * 16 + (lane >> 2);
#pragma unroll
            for (int ni = 0; ni < 4; ni++) {
                int col = bn + wn + ni * 8 + (lane & 3) * 2;
                *(float2*)(Cb + (size_t)rA * N + col)       = make_float2(acc[mi][ni][0], acc[mi][ni][1]);
                *(float2*)(Cb + (size_t)(rA + 8) * N + col) = make_float2(acc[mi][ni][2], acc[mi][ni][3]);
            }
        }
    } else {
        // transposed split: out rows = bn+d (length M), cols = bm..
        size_t base = (size_t)blockIdx.z * sO + (size_t)bn * M + bm;
        epi_splitT(acc, sm, wm, wn, lane, tid, OH, OL, base, M);
    }
}

// --------------------- dual-B GEMM (3-pass bf16x3) --------------------------
// C1 = A@B1^T, C2 = A@B2^T. GATE=1: write split(C1*C2) straight [M,N].
// GATE=0: write split-transpose of C1 and C2 into per-batch [Dv,Nv] arrays.
template<int GATE>
__global__ __launch_bounds__(GT, 1)
void gemm3_dual(const __nv_bfloat16* __restrict__ Ah, const __nv_bfloat16* __restrict__ Al,
                const __nv_bfloat16* __restrict__ B1h, const __nv_bfloat16* __restrict__ B1l,
                const __nv_bfloat16* __restrict__ B2h, const __nv_bfloat16* __restrict__ B2l,
                __nv_bfloat16* __restrict__ O1H, __nv_bfloat16* __restrict__ O1L,
                __nv_bfloat16* __restrict__ O2H, __nv_bfloat16* __restrict__ O2L,
                int N, int Kg)
{
    extern __shared__ char sm[];
    const uint32_t smu = s2u(sm);
    const int tid = threadIdx.x, lane = tid & 31, wid = tid >> 5;
    const int bm = blockIdx.y * 128, bn = blockIdx.x * 128;
    const int wm = (wid & 1) * 64, wn = (wid >> 1) * 32;

    const int rr = tid >> 2, cg = tid & 3;
    const uint32_t so0 = SWZ64((uint32_t)(rr * 64 + cg * 16));
    const uint32_t so1 = SWZ64((uint32_t)((rr + 64) * 64 + cg * 16));
    const __nv_bfloat16* gAh = Ah + (size_t)(bm + rr) * Kg + cg * 8;
    const __nv_bfloat16* gAl = Al + (size_t)(bm + rr) * Kg + cg * 8;
    const __nv_bfloat16* g1h = B1h + (size_t)(bn + rr) * Kg + cg * 8;
    const __nv_bfloat16* g1l = B1l + (size_t)(bn + rr) * Kg + cg * 8;
    const __nv_bfloat16* g2h = B2h + (size_t)(bn + rr) * Kg + cg * 8;
    const __nv_bfloat16* g2l = B2l + (size_t)(bn + rr) * Kg + cg * 8;
    const size_t rstep = (size_t)64 * Kg;

    uint32_t aoff[2][4], boff[2][2];
    {
        uint32_t arow = (uint32_t)(wm + (lane & 15));
        uint32_t acol = (uint32_t)((lane >> 4) * 16);
        uint32_t brow = (uint32_t)(wn + ((lane >> 4) << 3) + (lane & 7));
        uint32_t bcol = (uint32_t)(((lane >> 3) & 1) * 16);
#pragma unroll
        for (int ks = 0; ks < 2; ks++) {
#pragma unroll
            for (int mi = 0; mi < 4; mi++)
                aoff[ks][mi] = SWZ64((arow + mi * 16) * 64 + ks * 32 + acol);
#pragma unroll
            for (int g = 0; g < 2; g++)
                boff[ks][g] = SWZ64((brow + g * 16) * 64 + ks * 32 + bcol);
        }
    }

    float a1[4][4][4], a2[4][4][4];
#pragma unroll
    for (int mi = 0; mi < 4; mi++)
#pragma unroll
        for (int ni = 0; ni < 4; ni++)
#pragma unroll
            for (int j = 0; j < 4; j++) { a1[mi][ni][j] = 0.0f; a2[mi][ni][j] = 0.0f; }

    const int nch = Kg / 32;
    auto load_stage = [&](int c) {
        const uint32_t st = smu + (uint32_t)(c % NST2) * STAGE2;
        const int k0 = c * 32;
        cpa16(st + so0,          gAh + k0);
        cpa16(st + so1,          gAh + k0 + rstep);
        cpa16(st + ASZ + so0,    gAl + k0);
        cpa16(st + ASZ + so1,    gAl + k0 + rstep);
        cpa16(st + 2*ASZ + so0,  g1h + k0);
        cpa16(st + 2*ASZ + so1,  g1h + k0 + rstep);
        cpa16(st + 3*ASZ + so0,  g1l + k0);
        cpa16(st + 3*ASZ + so1,  g1l + k0 + rstep);
        cpa16(st + 4*ASZ + so0,  g2h + k0);
        cpa16(st + 4*ASZ + so1,  g2h + k0 + rstep);
        cpa16(st + 5*ASZ + so0,  g2l + k0);
        cpa16(st + 5*ASZ + so1,  g2l + k0 + rstep);
        CPC();
    };

    load_stage(0); load_stage(1);

    for (int c = 0; c < nch; ++c) {
        asm volatile("cp.async.wait_group 1;" ::: "memory");
        __syncthreads();
        if (c + 2 < nch) load_stage(c + 2);

        const uint32_t st = smu + (uint32_t)(c % NST2) * STAGE2;
#pragma unroll
        for (int ks = 0; ks < 2; ks++) {
            uint32_t ah[4][4], al[4][4];
#pragma unroll
            for (int mi = 0; mi < 4; mi++) {
                ldsm4(ah[mi], st + aoff[ks][mi]);
                ldsm4(al[mi], st + ASZ + aoff[ks][mi]);
            }
#pragma unroll
            for (int g = 0; g < 2; g++) {
                uint32_t t1h[4], t1l[4], t2h[4], t2l[4];
                ldsm4(t1h, st + 2*ASZ + boff[ks][g]);
                ldsm4(t1l, st + 3*ASZ + boff[ks][g]);
                ldsm4(t2h, st + 4*ASZ + boff[ks][g]);
                ldsm4(t2l, st + 5*ASZ + boff[ks][g]);
#pragma unroll
                for (int mi = 0; mi < 4; mi++) {
                    mma16816(a1[mi][2*g],   ah[mi], t1h);
                    mma16816(a1[mi][2*g],   ah[mi], t1l);
                    mma16816(a1[mi][2*g],   al[mi], t1h);
                    mma16816(a1[mi][2*g+1], ah[mi], t1h + 2);
                    mma16816(a1[mi][2*g+1], ah[mi], t1l + 2);
                    mma16816(a1[mi][2*g+1], al[mi], t1h + 2);
                    mma16816(a2[mi][2*g],   ah[mi], t2h);
                    mma16816(a2[mi][2*g],   ah[mi], t2l);
                    mma16816(a2[mi][2*g],   al[mi], t2h);
                    mma16816(a2[mi][2*g+1], ah[mi], t2h + 2);
                    mma16816(a2[mi][2*g+1], ah[mi], t2l + 2);
                    mma16816(a2[mi][2*g+1], al[mi], t2h + 2);
                }
            }
        }
    }

    if (GATE == 1) {
        // q = c1*c2, split, straight bf16 [row][col]
#pragma unroll
        for (int mi = 0; mi < 4; mi++) {
            int r = bm + wm + mi * 16 + (lane >> 2);
#pragma unroll
            for (int ni = 0; ni < 4; ni++) {
                int c = bn + wn + ni * 8 + (lane & 3) * 2;
                uint32_t wh, wl;
                split2pack(a1[mi][ni][0]*a2[mi][ni][0], a1[mi][ni][1]*a2[mi][ni][1], wh, wl);
                *(uint32_t*)(O1H + (size_t)r * N + c) = wh;
                *(uint32_t*)(O1L + (size_t)r * N + c) = wl;
                split2pack(a1[mi][ni][2]*a2[mi][ni][2], a1[mi][ni][3]*a2[mi][ni][3], wh, wl);
                *(uint32_t*)(O1H + (size_t)(r + 8) * N + c) = wh;
                *(uint32_t*)(O1L + (size_t)(r + 8) * N + c) = wl;
            }
        }
    } else {
        // split-transpose both C's into per-batch [Dv][Nv]
        size_t batch = (size_t)(bm >> 12);
        size_t base = batch * (size_t)Dv * Nv + (size_t)bn * Nv + (bm & 4095);
        epi_splitT(a1, sm, wm, wn, lane, tid, O1H, O1L, base, Nv);
        epi_splitT(a2, sm, wm, wn, lane, tid, O2H, O2L, base, Nv);
    }
}

// --------------------------- conversion kernels ----------------------------
__device__ __forceinline__ void split1(float f, __nv_bfloat16& h, __nv_bfloat16& l) {
    h = __float2bfloat16(f);
    l = __float2bfloat16(f - __bfloat162float(h));
}

__global__ void split_plain(const float* __restrict__ in,
                            __nv_bfloat16* __restrict__ oh, __nv_bfloat16* __restrict__ ol) {
    size_t i = (size_t)blockIdx.x * blockDim.x + threadIdx.x;
    float4 f = ((const float4*)in)[i];
    __nv_bfloat16 h0,h1,h2,h3,l0,l1,l2,l3;
    split1(f.x,h0,l0); split1(f.y,h1,l1); split1(f.z,h2,l2); split1(f.w,h3,l3);
    ((__nv_bfloat162*)oh)[i*2]   = __halves2bfloat162(h0,h1);
    ((__nv_bfloat162*)oh)[i*2+1] = __halves2bfloat162(h2,h3);
    ((__nv_bfloat162*)ol)[i*2]   = __halves2bfloat162(l0,l1);
    ((__nv_bfloat162*)ol)[i*2+1] = __halves2bfloat162(l2,l3);
}

// in [R,C] fp32 -> out [C,R] bf16 hi/lo (weights)
__global__ void split_transpose(const float* __restrict__ in,
                                __nv_bfloat16* __restrict__ oh, __nv_bfloat16* __restrict__ ol,
                                int R, int Cc) {
    __shared__ float t[32][33];
    int c0 = blockIdx.x * 32, r0 = blockIdx.y * 32;
    int tx = threadIdx.x, ty = threadIdx.y;
#pragma unroll
    for (int i = 0; i < 4; i++)
        t[ty + i*8][tx] = in[(size_t)(r0 + ty + i*8) * Cc + c0 + tx];
    __syncthreads();
#pragma unroll
    for (int i = 0; i < 4; i++) {
        int oc = c0 + ty + i*8, orow = r0 + tx;
        float f = t[tx][ty + i*8];
        __nv_bfloat16 h, l; split1(f, h, l);
        oh[(size_t)oc * R + orow] = h;
        ol[(size_t)oc * R + orow] = l;
    }
}

// ------------------------------- launch ------------------------------------
extern "C" void kernel_launch(void* const* d_in, const int* in_sizes, int n_in,
                              void* d_out, int out_size) {
    const float* x   = (const float*)d_in[0];
    const float* w[4] = { (const float*)d_in[1], (const float*)d_in[2],
                          (const float*)d_in[3], (const float*)d_in[4] };
    float* out = (float*)d_out;

    __nv_bfloat16 *XH,*XL,*WTH,*WTL,*QH,*QLo,*KTH,*KTL,*VTH,*VTL,*KVTH,*KVTL;
    cudaGetSymbolAddress((void**)&XH,  g_XH);   cudaGetSymbolAddress((void**)&XL,  g_XL);
    cudaGetSymbolAddress((void**)&WTH, g_WTH);  cudaGetSymbolAddress((void**)&WTL, g_WTL);
    cudaGetSymbolAddress((void**)&QH,  g_QH);   cudaGetSymbolAddress((void**)&QLo, g_QLo);
    cudaGetSymbolAddress((void**)&KTH, g_KTH);  cudaGetSymbolAddress((void**)&KTL, g_KTL);
    cudaGetSymbolAddress((void**)&VTH, g_VTH);  cudaGetSymbolAddress((void**)&VTL, g_VTL);
    cudaGetSymbolAddress((void**)&KVTH,g_KVTH); cudaGetSymbolAddress((void**)&KVTL,g_KVTL);

    cudaFuncSetAttribute(gemm3<0>,      cudaFuncAttributeMaxDynamicSharedMemorySize, SMEM1);
    cudaFuncSetAttribute(gemm3<1>,      cudaFuncAttributeMaxDynamicSharedMemorySize, SMEM1);
    cudaFuncSetAttribute(gemm3_dual<0>, cudaFuncAttributeMaxDynamicSharedMemorySize, SMEM2);
    cudaFuncSetAttribute(gemm3_dual<1>, cudaFuncAttributeMaxDynamicSharedMemorySize, SMEM2);

    const size_t DDe = (size_t)Dv * Dv;
    const size_t PNe = (size_t)BNROWS * Dv;
    dim3 tb32(32, 8);

    // 1) splits of x and W^T
    split_plain<<<(unsigned)(PNe/4/256), 256>>>(x, XH, XL);
    for (int i = 0; i < 4; i++)
        split_transpose<<<dim3(Dv/32, Dv/32), tb32>>>(w[i], WTH + i*DDe, WTL + i*DDe, Dv, Dv);

    // 2) fused projections: q = (x@Wql)*(x@Wqr) -> split straight
    gemm3_dual<1><<<dim3(Dv/128, BNROWS/128), GT, SMEM2>>>(
        XH, XL, WTH + 0*DDe, WTL + 0*DDe, WTH + 1*DDe, WTL + 1*DDe,
        QH, QLo, nullptr, nullptr, Dv, Dv);

    // 3) fused projections: k, v -> split-transposed [Dv,Nv] per batch
    gemm3_dual<0><<<dim3(Dv/128, BNROWS/128), GT, SMEM2>>>(
        XH, XL, WTH + 2*DDe, WTL + 2*DDe, WTH + 3*DDe, WTL + 3*DDe,
        KTH, KTL, VTH, VTL, Dv, Dv);

    // 4) kv[b] = k^T@v : A=kT[Dv,Nv], B=vT[Dv,Nv] -> kv^T split [Dv,Dv] per batch
    gemm3<1><<<dim3(Dv/128, Dv/128, Bv), GT, SMEM1>>>(
        KTH, KTL, VTH, VTL, nullptr, KVTH, KVTL,
        Dv, Dv, Nv, (long)Dv*Nv, (long)Dv*Nv, (long)DDe);

    // 5) out[b] = q@kv : A=q[Nv,Dv], B=kvT[Dv,Dv] -> fp32 out
    gemm3<0><<<dim3(Dv/128, Nv/128, Bv), GT, SMEM1>>>(
        QH, QLo, KVTH, KVTL, out, nullptr, nullptr,
        Nv, Dv, Dv, (long)Nv*Dv, (long)DDe, (long)Nv*Dv);
}